// round 17
// baseline (speedup 1.0000x reference)
#include <cuda_runtime.h>
#include <cuda_bf16.h>
#include <math.h>

typedef unsigned int       u32;
typedef unsigned long long u64;

#define N_NODES 50000
#define N_EDGES 800000
#define IN_DIM  128
#define HID_DIM 256
#define OUT_DIM 128

#define SCAN_BLK 256
#define N_SCAN_BLOCKS ((N_NODES + SCAN_BLK - 1) / SCAN_BLK)   // 196
#define N_TILES ((N_NODES + 127) / 128)                        // 391
#define M_PAD   (N_TILES * 128)                                // 50048

// GEMM staging: one stage = 4 arrays x 128 rows x 40 bf16 (pitch 80B)
#define STAGE_ELEMS (128 * 40)
#define SMEM_DYN    (2 * 4 * STAGE_ELEMS * 2)                  // 81920 B

// ---------------- scratch (device globals: no allocs allowed) ----------------
__device__ int   g_is64;
__device__ int   g_deg     [N_NODES];
__device__ int   g_blocksum[N_SCAN_BLOCKS];
__device__ int   g_rowstart[N_NODES + 1];
__device__ int   g_cursor  [N_NODES];
__device__ int   g_csr_src [N_EDGES];
__device__ float g_dinv    [N_NODES];
// split-bf16 operands (pad rows of g_a1_* stay zero; never written)
__device__ __nv_bfloat16 g_a1_hi[M_PAD * IN_DIM];
__device__ __nv_bfloat16 g_a1_lo[M_PAD * IN_DIM];
__device__ __nv_bfloat16 g_h1_hi[M_PAD * HID_DIM];
__device__ __nv_bfloat16 g_h1_lo[M_PAD * HID_DIM];
__device__ float g_h2s[M_PAD * OUT_DIM];
// W transposed [N][K] + bf16-split
__device__ __nv_bfloat16 g_w1t_hi[HID_DIM * IN_DIM];
__device__ __nv_bfloat16 g_w1t_lo[HID_DIM * IN_DIM];
__device__ __nv_bfloat16 g_w2t_hi[OUT_DIM * HID_DIM];
__device__ __nv_bfloat16 g_w2t_lo[OUT_DIM * HID_DIM];

// ---------------- helpers ----------------
__device__ __forceinline__ u32 smem_u32(const void* p) {
    u32 a;
    asm("{ .reg .u64 t; cvta.to.shared.u64 t, %1; cvt.u32.u64 %0, t; }" : "=r"(a) : "l"(p));
    return a;
}
__device__ __forceinline__ u32 pack_bf16x2(__nv_bfloat16 a, __nv_bfloat16 b) {
    u32 lo = (u32)__bfloat16_as_ushort(a);
    u32 hi = (u32)__bfloat16_as_ushort(b);
    return lo | (hi << 16);
}
__device__ __forceinline__ void split_f32(float v, __nv_bfloat16& hi, __nv_bfloat16& lo) {
    hi = __float2bfloat16(v);
    lo = __float2bfloat16(v - __bfloat162float(hi));
}
__device__ __forceinline__ void ldsm_x4(u32& r0, u32& r1, u32& r2, u32& r3, u32 addr) {
    asm volatile("ldmatrix.sync.aligned.m8n8.x4.shared.b16 {%0,%1,%2,%3}, [%4];"
                 : "=r"(r0), "=r"(r1), "=r"(r2), "=r"(r3) : "r"(addr));
}
__device__ __forceinline__ void mma_bf16(float& d0, float& d1, float& d2, float& d3,
                                         u32 a0, u32 a1, u32 a2, u32 a3, u32 b0, u32 b1) {
    asm volatile(
        "mma.sync.aligned.m16n8k16.row.col.f32.bf16.bf16.f32 "
        "{%0,%1,%2,%3}, {%4,%5,%6,%7}, {%8,%9}, {%0,%1,%2,%3};"
        : "+f"(d0), "+f"(d1), "+f"(d2), "+f"(d3)
        : "r"(a0), "r"(a1), "r"(a2), "r"(a3), "r"(b0), "r"(b1));
}
__device__ __forceinline__ void cp_async16(u32 saddr, const void* gptr) {
    asm volatile("cp.async.ca.shared.global [%0], [%1], 16;" :: "r"(saddr), "l"(gptr));
}
__device__ __forceinline__ void cp_commit() {
    asm volatile("cp.async.commit_group;" ::: "memory");
}
__device__ __forceinline__ void cp_wait1() {
    asm volatile("cp.async.wait_group 1;" ::: "memory");
}
__device__ __forceinline__ void cp_wait0() {
    asm volatile("cp.async.wait_group 0;" ::: "memory");
}
__device__ __forceinline__ void decode_edge(const int* __restrict__ ei, int e, int& s, int& d) {
    if (g_is64) {
        const long long* p = (const long long*)ei;
        s = (int)p[e];
        d = (int)p[N_EDGES + e];
    } else {
        s = ei[e];
        d = ei[N_EDGES + e];
    }
}

// ---------------- prep: detect dtype + zero deg/blocksum + convert both W ----------------
__global__ void __launch_bounds__(256) prep_kernel(
    const int* __restrict__ ei_raw,
    const float* __restrict__ W1,
    const float* __restrict__ W2)
{
    int i = blockIdx.x * 256 + threadIdx.x;

    if (blockIdx.x == 0) {
        __shared__ int s_or;
        if (threadIdx.x == 0) s_or = 0;
        __syncthreads();
        int v = ei_raw[2 * (threadIdx.x * 2) + 1] | ei_raw[2 * (threadIdx.x * 2 + 1) + 1];
        if (v) atomicOr(&s_or, 1);
        __syncthreads();
        if (threadIdx.x == 0) g_is64 = (s_or == 0) ? 1 : 0;
    }

    if (i < N_NODES) g_deg[i] = 0;
    if (i < N_SCAN_BLOCKS) g_blocksum[i] = 0;

    if (i < IN_DIM * HID_DIM) {
        int k = i / HID_DIM;
        int n = i % HID_DIM;
        __nv_bfloat16 hi, lo;
        split_f32(W1[i], hi, lo);
        g_w1t_hi[n * IN_DIM + k] = hi;
        g_w1t_lo[n * IN_DIM + k] = lo;
    }
    if (i < HID_DIM * OUT_DIM) {
        int k = i / OUT_DIM;
        int n = i % OUT_DIM;
        __nv_bfloat16 hi, lo;
        split_f32(W2[i], hi, lo);
        g_w2t_hi[n * HID_DIM + k] = hi;
        g_w2t_lo[n * HID_DIM + k] = lo;
    }
}

// ---------------- histogram of dst + warp-aggregated per-scan-block sums ----------------
// N_EDGES = 800000 = 3125 * 256 exactly: all warps are full, no tail mask issues.
__global__ void __launch_bounds__(256) hist_kernel(const int* __restrict__ ei_raw) {
    int e = blockIdx.x * blockDim.x + threadIdx.x;
    int s, d;
    decode_edge(ei_raw, e, s, d);
    atomicAdd(&g_deg[d], 1);

    int b = d >> 8;   // scan-block id (SCAN_BLK = 256)
    unsigned m = __match_any_sync(0xffffffffu, b);
    int lane = threadIdx.x & 31;
    int leader = __ffs(m) - 1;
    if (lane == leader) atomicAdd(&g_blocksum[b], __popc(m));
}

// ---------------- offsets: self-computed base from g_blocksum ----------------
__global__ void __launch_bounds__(SCAN_BLK) write_offsets_kernel() {
    __shared__ int sh[SCAN_BLK];
    __shared__ int s_warp[SCAN_BLK / 32];
    __shared__ int s_base;
    int tid = threadIdx.x;
    int bid = blockIdx.x;

    // base = sum of g_blocksum[0..bid)
    {
        int partial = 0;
        for (int j = tid; j < bid; j += SCAN_BLK) partial += g_blocksum[j];
        #pragma unroll
        for (int o = 16; o > 0; o >>= 1) partial += __shfl_down_sync(0xffffffffu, partial, o);
        if ((tid & 31) == 0) s_warp[tid >> 5] = partial;
        __syncthreads();
        if (tid == 0) {
            int b = 0;
            #pragma unroll
            for (int w = 0; w < SCAN_BLK / 32; w++) b += s_warp[w];
            s_base = b;
        }
    }

    int i = bid * SCAN_BLK + tid;
    int d = (i < N_NODES) ? g_deg[i] : 0;
    sh[tid] = d;
    __syncthreads();
    for (int ofs = 1; ofs < SCAN_BLK; ofs <<= 1) {
        int u = (tid >= ofs) ? sh[tid - ofs] : 0;
        __syncthreads();
        sh[tid] += u;
        __syncthreads();
    }
    if (i < N_NODES) {
        int start = s_base + sh[tid] - d;
        g_rowstart[i] = start;
        g_cursor[i]   = start;
        g_dinv[i]     = rsqrtf((float)d + 1.0f);
    }
    if (bid == N_SCAN_BLOCKS - 1 && tid == SCAN_BLK - 1)
        g_rowstart[N_NODES] = s_base + sh[tid];
}

__global__ void fill_csr_kernel(const int* __restrict__ ei_raw) {
    int e = blockIdx.x * blockDim.x + threadIdx.x;
    if (e >= N_EDGES) return;
    int s, d;
    decode_edge(ei_raw, e, s, d);
    int pos = atomicAdd(&g_cursor[d], 1);
    g_csr_src[pos] = s;
}

// ---------------- aggX: split-bf16 out of dinv[d]*(sum dinv[s]*x[s] + dinv[d]*x[d]) ----------------
// 4-edge unroll: 4 independent float4 gathers in flight per lane.
__global__ void __launch_bounds__(256) aggx_kernel(const float* __restrict__ X)
{
    int node = ((blockIdx.x * blockDim.x + threadIdx.x) >> 5);
    int lane = threadIdx.x & 31;
    if (node >= N_NODES) return;

    int beg = g_rowstart[node];
    int end = g_rowstart[node + 1];
    int c = lane * 4;

    float wd = g_dinv[node];
    float4 v = *(const float4*)(X + (size_t)node * IN_DIM + c);
    float4 a = make_float4(v.x * wd, v.y * wd, v.z * wd, v.w * wd);

    int e = beg;
    for (; e + 3 < end; e += 4) {
        int s0 = g_csr_src[e];
        int s1 = g_csr_src[e + 1];
        int s2 = g_csr_src[e + 2];
        int s3 = g_csr_src[e + 3];
        float w0 = g_dinv[s0];
        float w1 = g_dinv[s1];
        float w2 = g_dinv[s2];
        float w3 = g_dinv[s3];
        float4 v0 = *(const float4*)(X + (size_t)s0 * IN_DIM + c);
        float4 v1 = *(const float4*)(X + (size_t)s1 * IN_DIM + c);
        float4 v2 = *(const float4*)(X + (size_t)s2 * IN_DIM + c);
        float4 v3 = *(const float4*)(X + (size_t)s3 * IN_DIM + c);
        a.x = fmaf(v0.x, w0, fmaf(v1.x, w1, fmaf(v2.x, w2, fmaf(v3.x, w3, a.x))));
        a.y = fmaf(v0.y, w0, fmaf(v1.y, w1, fmaf(v2.y, w2, fmaf(v3.y, w3, a.y))));
        a.z = fmaf(v0.z, w0, fmaf(v1.z, w1, fmaf(v2.z, w2, fmaf(v3.z, w3, a.z))));
        a.w = fmaf(v0.w, w0, fmaf(v1.w, w1, fmaf(v2.w, w2, fmaf(v3.w, w3, a.w))));
    }
    for (; e < end; e++) {
        int s0 = g_csr_src[e];
        float w0 = g_dinv[s0];
        float4 v0 = *(const float4*)(X + (size_t)s0 * IN_DIM + c);
        a.x = fmaf(v0.x, w0, a.x);
        a.y = fmaf(v0.y, w0, a.y);
        a.z = fmaf(v0.z, w0, a.z);
        a.w = fmaf(v0.w, w0, a.w);
    }

    a.x *= wd; a.y *= wd; a.z *= wd; a.w *= wd;

    __nv_bfloat16 h0, l0, h1, l1, h2, l2, h3, l3;
    split_f32(a.x, h0, l0);
    split_f32(a.y, h1, l1);
    split_f32(a.z, h2, l2);
    split_f32(a.w, h3, l3);
    uint2 hv, lv;
    hv.x = pack_bf16x2(h0, h1); hv.y = pack_bf16x2(h2, h3);
    lv.x = pack_bf16x2(l0, l1); lv.y = pack_bf16x2(l2, l3);
    *(uint2*)(g_a1_hi + (size_t)node * IN_DIM + c) = hv;
    *(uint2*)(g_a1_lo + (size_t)node * IN_DIM + c) = lv;
}

// ---------------- mma.sync split-bf16 GEMM, cp.async double-buffered ----------------
// C[M,NDIM] = A[M,KDIM] @ Wt[NDIM,KDIM]^T  (3-term split accumulation)
// SPLIT_OUT: C' = relu(C + bias) split-> (Chi, Clo) bf16;  else: Cf = C * dinv[row]
template <int KDIM, int NDIM, bool SPLIT_OUT>
__device__ __forceinline__ void mma_gemm_body(
    const __nv_bfloat16* __restrict__ Ahi, const __nv_bfloat16* __restrict__ Alo,
    const __nv_bfloat16* __restrict__ Whi, const __nv_bfloat16* __restrict__ Wlo,
    const float* __restrict__ bias,
    __nv_bfloat16* __restrict__ Chi, __nv_bfloat16* __restrict__ Clo,
    float* __restrict__ Cf)
{
    extern __shared__ __nv_bfloat16 smem_dyn[];
    const int tid    = threadIdx.x;      // 256 threads
    const int lane   = tid & 31;
    const int warp   = tid >> 5;
    const int warp_m = warp & 3;
    const int warp_n = warp >> 2;
    const int bm     = blockIdx.x * 128;
    const int bn     = blockIdx.y * 128;

    float acc[2][8][4];
    #pragma unroll
    for (int i = 0; i < 2; i++)
        #pragma unroll
        for (int j = 0; j < 8; j++)
            #pragma unroll
            for (int q = 0; q < 4; q++) acc[i][j][q] = 0.f;

    u32 sbase[2][4];
    #pragma unroll
    for (int st = 0; st < 2; st++)
        #pragma unroll
        for (int ar = 0; ar < 4; ar++)
            sbase[st][ar] = smem_u32(smem_dyn + (st * 4 + ar) * STAGE_ELEMS);

    const int row0 = tid >> 2;
    const int c40  = (tid & 3) * 8;

    const int a_lr = lane & 15;
    const int a_ko = (lane < 16) ? 0 : 8;
    const int b_l8 = lane & 7;
    const int b_gr = lane >> 3;
    const int b_nrow = (b_gr & 2) ? (b_l8 + 8) : b_l8;
    const int b_ko   = (b_gr & 1) ? 8 : 0;

    const int KC = KDIM / 32;

    auto stage_load = [&](int st, int kc) {
        #pragma unroll
        for (int l = 0; l < 2; l++) {
            int row = row0 + l * 64;
            size_t ga = (size_t)(bm + row) * KDIM + kc * 32 + c40;
            size_t gb = (size_t)(bn + row) * KDIM + kc * 32 + c40;
            u32 so = (u32)(row * 40 + c40) * 2;
            cp_async16(sbase[st][0] + so, Ahi + ga);
            cp_async16(sbase[st][1] + so, Alo + ga);
            cp_async16(sbase[st][2] + so, Whi + gb);
            cp_async16(sbase[st][3] + so, Wlo + gb);
        }
        cp_commit();
    };

    stage_load(0, 0);

    for (int kc = 0; kc < KC; kc++) {
        int st = kc & 1;
        if (kc + 1 < KC) {
            stage_load(st ^ 1, kc + 1);
            cp_wait1();
        } else {
            cp_wait0();
        }
        __syncthreads();

        const u32 sAh_b = sbase[st][0];
        const u32 sAl_b = sbase[st][1];
        const u32 sBh_b = sbase[st][2];
        const u32 sBl_b = sbase[st][3];

        #pragma unroll
        for (int ks = 0; ks < 32; ks += 16) {
            u32 ah[2][4], al[2][4];
            #pragma unroll
            for (int mt = 0; mt < 2; mt++) {
                u32 off = (u32)((warp_m * 32 + mt * 16 + a_lr) * 40 + ks + a_ko) * 2;
                ldsm_x4(ah[mt][0], ah[mt][1], ah[mt][2], ah[mt][3], sAh_b + off);
                ldsm_x4(al[mt][0], al[mt][1], al[mt][2], al[mt][3], sAl_b + off);
            }
            u32 bh[8][2], bl[8][2];
            #pragma unroll
            for (int ntp = 0; ntp < 4; ntp++) {
                u32 off = (u32)((warp_n * 64 + ntp * 16 + b_nrow) * 40 + ks + b_ko) * 2;
                ldsm_x4(bh[2 * ntp][0], bh[2 * ntp][1], bh[2 * ntp + 1][0], bh[2 * ntp + 1][1], sBh_b + off);
                ldsm_x4(bl[2 * ntp][0], bl[2 * ntp][1], bl[2 * ntp + 1][0], bl[2 * ntp + 1][1], sBl_b + off);
            }
            #pragma unroll
            for (int mt = 0; mt < 2; mt++) {
                #pragma unroll
                for (int nt = 0; nt < 8; nt++) {
                    float* d = acc[mt][nt];
                    mma_bf16(d[0], d[1], d[2], d[3],
                             ah[mt][0], ah[mt][1], ah[mt][2], ah[mt][3],
                             bh[nt][0], bh[nt][1]);
                    mma_bf16(d[0], d[1], d[2], d[3],
                             ah[mt][0], ah[mt][1], ah[mt][2], ah[mt][3],
                             bl[nt][0], bl[nt][1]);
                    mma_bf16(d[0], d[1], d[2], d[3],
                             al[mt][0], al[mt][1], al[mt][2], al[mt][3],
                             bh[nt][0], bh[nt][1]);
                }
            }
        }
        __syncthreads();
    }

    // ---- epilogue ----
    const int g   = lane >> 2;
    const int tig = lane & 3;
    #pragma unroll
    for (int mt = 0; mt < 2; mt++) {
        int r0 = bm + warp_m * 32 + mt * 16 + g;
        int r1 = r0 + 8;
        #pragma unroll
        for (int nt = 0; nt < 8; nt++) {
            int col = bn + warp_n * 64 + nt * 8 + tig * 2;
            float c0 = acc[mt][nt][0];
            float c1 = acc[mt][nt][1];
            float c2 = acc[mt][nt][2];
            float c3 = acc[mt][nt][3];
            if (SPLIT_OUT) {
                float bb0 = bias[col];
                float bb1 = bias[col + 1];
                float v0 = fmaxf(c0 + bb0, 0.f);
                float v1 = fmaxf(c1 + bb1, 0.f);
                float v2 = fmaxf(c2 + bb0, 0.f);
                float v3 = fmaxf(c3 + bb1, 0.f);
                __nv_bfloat16 h0, l0, h1, l1;
                split_f32(v0, h0, l0);
                split_f32(v1, h1, l1);
                *(u32*)(Chi + (size_t)r0 * NDIM + col) = pack_bf16x2(h0, h1);
                *(u32*)(Clo + (size_t)r0 * NDIM + col) = pack_bf16x2(l0, l1);
                split_f32(v2, h0, l0);
                split_f32(v3, h1, l1);
                *(u32*)(Chi + (size_t)r1 * NDIM + col) = pack_bf16x2(h0, h1);
                *(u32*)(Clo + (size_t)r1 * NDIM + col) = pack_bf16x2(l0, l1);
            } else {
                float s0 = (r0 < N_NODES) ? g_dinv[r0] : 0.f;
                float s1 = (r1 < N_NODES) ? g_dinv[r1] : 0.f;
                float2 o0 = make_float2(c0 * s0, c1 * s0);
                float2 o1 = make_float2(c2 * s1, c3 * s1);
                *(float2*)(Cf + (size_t)r0 * NDIM + col) = o0;
                *(float2*)(Cf + (size_t)r1 * NDIM + col) = o1;
            }
        }
    }
}

__global__ void __launch_bounds__(256) mma_gemm1_kernel(const float* __restrict__ b1)
{
    mma_gemm_body<IN_DIM, HID_DIM, true>(g_a1_hi, g_a1_lo, g_w1t_hi, g_w1t_lo,
                                         b1, g_h1_hi, g_h1_lo, (float*)0);
}

__global__ void __launch_bounds__(256) mma_gemm2_kernel()
{
    mma_gemm_body<HID_DIM, OUT_DIM, false>(g_h1_hi, g_h1_lo, g_w2t_hi, g_w2t_lo,
                                           (const float*)0, (__nv_bfloat16*)0, (__nv_bfloat16*)0, g_h2s);
}

// ---------------- agg2: out[d] = dinv[d]*(sum h2s[src] + h2s[d]) + b2 ----------------
// 4-edge unroll
__global__ void __launch_bounds__(256) agg2_kernel(
    const float* __restrict__ b2,
    float* __restrict__ out)
{
    int node = ((blockIdx.x * blockDim.x + threadIdx.x) >> 5);
    int lane = threadIdx.x & 31;
    if (node >= N_NODES) return;

    int beg = g_rowstart[node];
    int end = g_rowstart[node + 1];
    int c0 = lane * 4;

    float4 a0 = *(const float4*)(g_h2s + (size_t)node * OUT_DIM + c0);

    int e = beg;
    for (; e + 3 < end; e += 4) {
        int s0 = g_csr_src[e];
        int s1 = g_csr_src[e + 1];
        int s2 = g_csr_src[e + 2];
        int s3 = g_csr_src[e + 3];
        float4 v0 = *(const float4*)(g_h2s + (size_t)s0 * OUT_DIM + c0);
        float4 v1 = *(const float4*)(g_h2s + (size_t)s1 * OUT_DIM + c0);
        float4 v2 = *(const float4*)(g_h2s + (size_t)s2 * OUT_DIM + c0);
        float4 v3 = *(const float4*)(g_h2s + (size_t)s3 * OUT_DIM + c0);
        a0.x += (v0.x + v1.x) + (v2.x + v3.x);
        a0.y += (v0.y + v1.y) + (v2.y + v3.y);
        a0.z += (v0.z + v1.z) + (v2.z + v3.z);
        a0.w += (v0.w + v1.w) + (v2.w + v3.w);
    }
    for (; e < end; e++) {
        int s0 = g_csr_src[e];
        float4 v0 = *(const float4*)(g_h2s + (size_t)s0 * OUT_DIM + c0);
        a0.x += v0.x; a0.y += v0.y; a0.z += v0.z; a0.w += v0.w;
    }

    float w = g_dinv[node];
    float4 bb = *(const float4*)(b2 + c0);
    a0.x = a0.x * w + bb.x;
    a0.y = a0.y * w + bb.y;
    a0.z = a0.z * w + bb.z;
    a0.w = a0.w * w + bb.w;
    *(float4*)(out + (size_t)node * OUT_DIM + c0) = a0;
}

// ---------------- launch ----------------
extern "C" void kernel_launch(void* const* d_in, const int* in_sizes, int n_in,
                              void* d_out, int out_size)
{
    const float* x  = (const float*)d_in[0];
    const int*   ei = (const int*)d_in[1];
    const float* W1 = (const float*)d_in[2];
    const float* b1 = (const float*)d_in[3];
    const float* W2 = (const float*)d_in[4];
    const float* b2 = (const float*)d_in[5];
    float* out = (float*)d_out;

    cudaFuncSetAttribute(mma_gemm1_kernel, cudaFuncAttributeMaxDynamicSharedMemorySize, SMEM_DYN);
    cudaFuncSetAttribute(mma_gemm2_kernel, cudaFuncAttributeMaxDynamicSharedMemorySize, SMEM_DYN);

    // preprocessing: detect + zero + convert W (one kernel), then CSR build (3 kernels)
    prep_kernel<<<N_SCAN_BLOCKS, 256>>>(ei, W1, W2);
    hist_kernel<<<N_EDGES / 256, 256>>>(ei);
    write_offsets_kernel<<<N_SCAN_BLOCKS, SCAN_BLK>>>();
    fill_csr_kernel<<<(N_EDGES + 255) / 256, 256>>>(ei);

    // layer 1: aggregate (split-bf16 out) then HMMA GEMM (fused relu+b1, split-bf16 out)
    aggx_kernel<<<(N_NODES + 7) / 8, 256>>>(x);
    {
        dim3 grid(N_TILES, HID_DIM / 128);
        mma_gemm1_kernel<<<grid, 256, SMEM_DYN>>>(b1);
    }

    // layer 2: HMMA GEMM (*dinv epilogue) then aggregate
    {
        dim3 grid(N_TILES, OUT_DIM / 128);
        mma_gemm2_kernel<<<grid, 256, SMEM_DYN>>>();
    }
    agg2_kernel<<<(N_NODES + 7) / 8, 256>>>(b2, out);
}